// round 14
// baseline (speedup 1.0000x reference)
#include <cuda_runtime.h>
#include <cstdint>
#include <cstddef>

typedef unsigned long long ull;

// ---------------- constants ----------------
#define BB   256
#define SS   512
#define DD   200
#define HH   256
#define NJ   1024          // 4*H packed gate columns
#define NGRP 16            // batch groups (16 rows each)
#define NPAIR 8            // group pairs; CTA serves both groups of a pair

// ---------------- device scratch ----------------
__device__ float    g_G[134217728];   // [B][S][1024] gate preactivations (x part + bias)
__device__ float    g_Wxp[DD * NJ];   // packed x-weights  [200][1024]
__device__ float    g_Whp[8 * 32768]; // packed h-weights  [colgrp][256][128]
__device__ float    g_biasp[NJ];
__device__ float    g_hbuf[2 * 65536];   // [parity][group][col 256][row 16]
__device__ ull      g_flags[16];         // [pair][word]: 4x16-bit producer counters each

// ---------------- helpers ----------------
__device__ __forceinline__ ull pk2(float lo, float hi) {
    ull r; asm("mov.b64 %0,{%1,%2};" : "=l"(r) : "f"(lo), "f"(hi)); return r;
}
__device__ __forceinline__ void upk2(ull v, float& lo, float& hi) {
    asm("mov.b64 {%0,%1},%2;" : "=f"(lo), "=f"(hi) : "l"(v));
}
__device__ __forceinline__ ull ffma2(ull a, ull b, ull c) {
    ull d; asm("fma.rn.f32x2 %0,%1,%2,%3;" : "=l"(d) : "l"(a), "l"(b), "l"(c)); return d;
}
__device__ __forceinline__ float sigf(float x) {
    return __fdividef(1.0f, 1.0f + __expf(-x));
}
__device__ __forceinline__ float tanhfast(float x) {
    return __fdividef(2.0f, 1.0f + __expf(-2.0f * x)) - 1.0f;
}
__device__ __forceinline__ ull ldacq64(const ull* p) {
    ull v;
    asm volatile("ld.global.acquire.gpu.u64 %0,[%1];" : "=l"(v) : "l"(p) : "memory");
    return v;
}
__device__ __forceinline__ void red_release64(ull* p, ull v) {
    asm volatile("red.release.gpu.global.add.u64 [%0], %1;" :: "l"(p), "l"(v) : "memory");
}

// ---------------- kernel 0: pack weights ----------------
// j = g*128 + c*4 + gate  (g: col group 0..7, c: col-in-group 0..31, gate: i,f,o,z)
__global__ void k_pack(const float* __restrict__ Wi, const float* __restrict__ Wf,
                       const float* __restrict__ Wo, const float* __restrict__ Wz,
                       const float* __restrict__ bi, const float* __restrict__ bf,
                       const float* __restrict__ bo, const float* __restrict__ bz) {
    int idx = blockIdx.x * blockDim.x + threadIdx.x;
    if (idx < 456 * NJ) {
        int k = idx >> 10;
        int j = idx & (NJ - 1);
        int gate = j & 3;
        int c    = (j >> 2) & 31;
        int g    = j >> 7;
        int col  = g * 32 + c;
        const float* W = (gate == 0) ? Wi : (gate == 1) ? Wf : (gate == 2) ? Wo : Wz;
        float v = W[k * HH + col];
        if (k < DD) g_Wxp[k * NJ + j] = v;
        else        g_Whp[g * 32768 + (k - DD) * 128 + (j & 127)] = v;
    }
    if (idx < NJ) {
        int gate = idx & 3;
        int c    = (idx >> 2) & 31;
        int g    = idx >> 7;
        int col  = g * 32 + c;
        const float* bb = (gate == 0) ? bi : (gate == 1) ? bf : (gate == 2) ? bo : bz;
        g_biasp[idx] = bb[col];
    }
}

// ---------------- kernel 1: reset flags ----------------
__global__ void k_reset() {
    int i = threadIdx.x;
    if (i < 16) g_flags[i] = 0ull;
}

// ---------------- kernel 2: G = X @ Wxp + bias (EXACT R4/R10 version) ----------------
#define G1_BM 128
#define G1_BN 64
#define G1_BK 8
__global__ void __launch_bounds__(256) k_gemm1(const float* __restrict__ x) {
    __shared__ __align__(16) float As[2][G1_BK][G1_BM];
    __shared__ __align__(16) float Bs[2][G1_BK][G1_BN];

    int tid = threadIdx.x;
    int m0 = blockIdx.y * G1_BM;
    int n0 = blockIdx.x * G1_BN;

    int arow = tid >> 1;
    int akq  = (tid & 1) * 4;
    const float* aptr = x + (size_t)(m0 + arow) * DD + akq;

    int bkk = tid >> 5;
    int bn  = (tid & 31) * 2;
    const float* bptr = g_Wxp + (size_t)bkk * NJ + n0 + bn;

    int tx = tid & 15;   // 4 n-cols
    int ty = tid >> 4;   // 8 m-rows

    ull acc[4][4];
#pragma unroll
    for (int i = 0; i < 4; ++i)
#pragma unroll
        for (int j = 0; j < 4; ++j) acc[i][j] = 0ull;

    float4 av = *(const float4*)aptr;
    float2 bv = *(const float2*)bptr;
    As[0][akq + 0][arow] = av.x;
    As[0][akq + 1][arow] = av.y;
    As[0][akq + 2][arow] = av.z;
    As[0][akq + 3][arow] = av.w;
    *(float2*)&Bs[0][bkk][bn] = bv;

    for (int kc = 0; kc < 25; ++kc) {
        __syncthreads();
        int cur = kc & 1;
        if (kc < 24) {
            av = *(const float4*)(aptr + (kc + 1) * G1_BK);
            bv = *(const float2*)(bptr + (size_t)(kc + 1) * G1_BK * NJ);
        }
#pragma unroll
        for (int kk = 0; kk < G1_BK; ++kk) {
            const ull* ap2 = (const ull*)&As[cur][kk][ty * 8];
            ull A0 = ap2[0], A1 = ap2[1], A2 = ap2[2], A3 = ap2[3];
            float4 b4 = *(const float4*)&Bs[cur][kk][tx * 4];
            ull B0 = pk2(b4.x, b4.x), B1 = pk2(b4.y, b4.y);
            ull B2 = pk2(b4.z, b4.z), B3 = pk2(b4.w, b4.w);
            acc[0][0] = ffma2(A0, B0, acc[0][0]); acc[0][1] = ffma2(A0, B1, acc[0][1]);
            acc[0][2] = ffma2(A0, B2, acc[0][2]); acc[0][3] = ffma2(A0, B3, acc[0][3]);
            acc[1][0] = ffma2(A1, B0, acc[1][0]); acc[1][1] = ffma2(A1, B1, acc[1][1]);
            acc[1][2] = ffma2(A1, B2, acc[1][2]); acc[1][3] = ffma2(A1, B3, acc[1][3]);
            acc[2][0] = ffma2(A2, B0, acc[2][0]); acc[2][1] = ffma2(A2, B1, acc[2][1]);
            acc[2][2] = ffma2(A2, B2, acc[2][2]); acc[2][3] = ffma2(A2, B3, acc[2][3]);
            acc[3][0] = ffma2(A3, B0, acc[3][0]); acc[3][1] = ffma2(A3, B1, acc[3][1]);
            acc[3][2] = ffma2(A3, B2, acc[3][2]); acc[3][3] = ffma2(A3, B3, acc[3][3]);
        }
        if (kc < 24) {
            int nxt = cur ^ 1;
            As[nxt][akq + 0][arow] = av.x;
            As[nxt][akq + 1][arow] = av.y;
            As[nxt][akq + 2][arow] = av.z;
            As[nxt][akq + 3][arow] = av.w;
            *(float2*)&Bs[nxt][bkk][bn] = bv;
        }
    }

    float4 bias4 = *(const float4*)(g_biasp + n0 + tx * 4);
#pragma unroll
    for (int rp = 0; rp < 4; ++rp) {
        float4 r0, r1;
        upk2(acc[rp][0], r0.x, r1.x);
        upk2(acc[rp][1], r0.y, r1.y);
        upk2(acc[rp][2], r0.z, r1.z);
        upk2(acc[rp][3], r0.w, r1.w);
        r0.x += bias4.x; r0.y += bias4.y; r0.z += bias4.z; r0.w += bias4.w;
        r1.x += bias4.x; r1.y += bias4.y; r1.z += bias4.z; r1.w += bias4.w;
        size_t mrow = (size_t)m0 + ty * 8 + rp * 2;
        __stcs((float4*)(g_G + mrow * NJ + n0 + tx * 4), r0);
        __stcs((float4*)(g_G + (mrow + 1) * NJ + n0 + tx * 4), r1);
    }
}

// ---------------- kernel 3: persistent recurrence, two groups per CTA ----------------
// 64 CTAs = 8 pairs x 8 col-CTAs. Ws (128KB) shared by both groups of the pair.
// Per iter: one poll+release for the pair; gather both; matvec A hides B's LDG;
// epilogue A hides under pre-matvec-B bar. Matvec body = proven R10 code.
// smem: Ws 131072 | stgA 16384 | stgB 16384 = 163840 B
#define REC_SMEM_BYTES (131072 + 16384 + 16384)
__global__ void __launch_bounds__(256, 1) k_rec(const float* __restrict__ mask,
                                                float* __restrict__ out) {
    extern __shared__ __align__(16) float sm[];
    float*  Ws   = sm;                       // [256 k][128 j]
    float4* stgA = (float4*)(sm + 32768);    // [128 k2][8 rp], slot k2*8 + (rp^(k2&7))
    float4* stgB = stgA + 1024;

    int tid = threadIdx.x;
    int pair = blockIdx.x >> 3;
    int g    = blockIdx.x & 7;
    int grpA = pair * 2, grpB = pair * 2 + 1;
    int rp  = tid & 7;    // row pair: rows 2rp, 2rp+1
    int cq  = tid >> 3;   // hidden col in slice 0..31

    // preload weight slice (once for all 512 steps; shared by both groups)
    {
        const float4* wsrc = (const float4*)(g_Whp + (size_t)g * 32768);
        float4* wdst = (float4*)Ws;
        for (int i = tid; i < 8192; i += 256) wdst[i] = wsrc[i];
    }
    __syncthreads();

    int bA = grpA * 16 + rp * 2;
    int bB = grpB * 16 + rp * 2;
    float cA0 = 0.f, cA1 = 0.f, sA0 = 0.f, sA1 = 0.f, mA0 = 0.f, mA1 = 0.f;
    float cB0 = 0.f, cB1 = 0.f, sB0 = 0.f, sB1 = 0.f, mB0 = 0.f, mB1 = 0.f;
    const float* gbA = g_G + (size_t)bA * SS * NJ + g * 128 + cq * 4;
    const float* gbB = g_G + (size_t)bB * SS * NJ + g * 128 + cq * 4;
    const float* mkA = mask + (size_t)bA * SS;
    const float* mkB = mask + (size_t)bB * SS;
    ull* flagw = &g_flags[pair * 2];
    ull  myinc = 1ull << (16 * (g & 3));
    int  myw   = g >> 2;

    // gather decode: 4 entries per thread per group, e = tid + q*256
    int k2l = (tid >> 3) & 15;
    int spb = tid >> 7;                      // 0..1
    int slot0 = ((spb * 16) + k2l) * 8 + (rp ^ (k2l & 7));   // q adds sp+=2 -> slot += 256

    for (int s = 0; s < SS; ++s) {
        // prefetch this step's x-gate preactivations + masks (independent of h)
        float4 gaA = __ldcs((const float4*)(gbA + (size_t)s * NJ));
        float4 gbA4 = __ldcs((const float4*)(gbA + (size_t)SS * NJ + (size_t)s * NJ));
        float4 gaB = __ldcs((const float4*)(gbB + (size_t)s * NJ));
        float4 gbB4 = __ldcs((const float4*)(gbB + (size_t)SS * NJ + (size_t)s * NJ));
        float mvA0 = __ldg(mkA + s), mvA1 = __ldg(mkA + SS + s);
        float mvB0 = __ldg(mkB + s), mvB1 = __ldg(mkB + SS + s);

        float2 vA0[4], vA1[4], vB0[4], vB1[4];
        if (s) {
            // single poll for the pair: all 8 producer fields >= s
            if (tid == 0) {
                unsigned us = (unsigned)s;
                for (;;) {
                    ull w0 = ldacq64(flagw);
                    ull w1 = ldacq64(flagw + 1);
                    if ((unsigned)(w0 & 0xFFFF) >= us &&
                        (unsigned)((w0 >> 16) & 0xFFFF) >= us &&
                        (unsigned)((w0 >> 32) & 0xFFFF) >= us &&
                        (unsigned)((w0 >> 48) & 0xFFFF) >= us &&
                        (unsigned)(w1 & 0xFFFF) >= us &&
                        (unsigned)((w1 >> 16) & 0xFFFF) >= us &&
                        (unsigned)((w1 >> 32) & 0xFFFF) >= us &&
                        (unsigned)((w1 >> 48) & 0xFFFF) >= us)
                        break;
                }
            }
            __syncthreads();

            // issue ALL gather LDGs for both groups upfront (16x LDG.64)
            const float* hbA = g_hbuf + ((size_t)(s & 1)) * 65536 + (size_t)grpA * 4096;
            const float* hbB = g_hbuf + ((size_t)(s & 1)) * 65536 + (size_t)grpB * 4096;
#pragma unroll
            for (int q = 0; q < 4; ++q) {
                int sp = spb + q * 2;
                int off = (sp * 32 + k2l * 2) * 16 + rp * 2;
                vA0[q] = __ldcg((const float2*)(hbA + off));
                vA1[q] = __ldcg((const float2*)(hbA + off + 16));
                vB0[q] = __ldcg((const float2*)(hbB + off));
                vB1[q] = __ldcg((const float2*)(hbB + off + 16));
            }
        }

        ull a00 = pk2(gaA.x, gaA.y), a01 = pk2(gaA.z, gaA.w);
        ull a10 = pk2(gbA4.x, gbA4.y), a11 = pk2(gbA4.z, gbA4.w);
        ull b00 = pk2(gaB.x, gaB.y), b01 = pk2(gaB.z, gaB.w);
        ull b10 = pk2(gbB4.x, gbB4.y), b11 = pk2(gbB4.z, gbB4.w);

        if (s) {
            // stage A, then matvec A while B's LDGs land
#pragma unroll
            for (int q = 0; q < 4; ++q)
                stgA[slot0 + q * 256] = make_float4(vA0[q].x, vA0[q].y, vA1[q].x, vA1[q].y);
            __syncthreads();

            const ulonglong2* wq = (const ulonglong2*)Ws + cq;   // row k at +k*32
#pragma unroll 8
            for (int k2 = 0; k2 < 128; ++k2) {
                ulonglong2 w0 = wq[k2 * 64];
                ulonglong2 w1 = wq[k2 * 64 + 32];
                float4 h4 = stgA[k2 * 8 + (rp ^ (k2 & 7))];
                ull ha0 = pk2(h4.x, h4.x), hb0 = pk2(h4.y, h4.y);
                ull ha1 = pk2(h4.z, h4.z), hb1 = pk2(h4.w, h4.w);
                a00 = ffma2(ha0, w0.x, a00); a01 = ffma2(ha0, w0.y, a01);
                a10 = ffma2(hb0, w0.x, a10); a11 = ffma2(hb0, w0.y, a11);
                a00 = ffma2(ha1, w1.x, a00); a01 = ffma2(ha1, w1.y, a01);
                a10 = ffma2(hb1, w1.x, a10); a11 = ffma2(hb1, w1.y, a11);
            }

            // stage B
#pragma unroll
            for (int q = 0; q < 4; ++q)
                stgB[slot0 + q * 256] = make_float4(vB0[q].x, vB0[q].y, vB1[q].x, vB1[q].y);
        }

        // epilogue A + publish A (hides under pre-matvec-B bar)
        {
            float ai0, af0, ao0, az0, ai1, af1, ao1, az1;
            upk2(a00, ai0, af0); upk2(a01, ao0, az0);
            upk2(a10, ai1, af1); upk2(a11, ao1, az1);
            float i0 = sigf(ai0), f0 = sigf(af0), o0 = sigf(ao0), z0 = tanhfast(az0);
            cA0 = i0 * z0 + f0 * cA0;
            float h0 = o0 * tanhfast(cA0);
            float i1 = sigf(ai1), f1 = sigf(af1), o1 = sigf(ao1), z1 = tanhfast(az1);
            cA1 = i1 * z1 + f1 * cA1;
            float h1 = o1 * tanhfast(cA1);
            sA0 += h0 * mvA0; mA0 += mvA0;
            sA1 += h1 * mvA1; mA1 += mvA1;
            float2 hv; hv.x = h0; hv.y = h1;
            __stcg((float2*)(g_hbuf + ((size_t)((s + 1) & 1)) * 65536 +
                             (size_t)grpA * 4096 + (size_t)(g * 32 + cq) * 16 + rp * 2),
                   hv);
        }

        if (s) {
            __syncthreads();
            const ulonglong2* wq = (const ulonglong2*)Ws + cq;
#pragma unroll 8
            for (int k2 = 0; k2 < 128; ++k2) {
                ulonglong2 w0 = wq[k2 * 64];
                ulonglong2 w1 = wq[k2 * 64 + 32];
                float4 h4 = stgB[k2 * 8 + (rp ^ (k2 & 7))];
                ull ha0 = pk2(h4.x, h4.x), hb0 = pk2(h4.y, h4.y);
                ull ha1 = pk2(h4.z, h4.z), hb1 = pk2(h4.w, h4.w);
                b00 = ffma2(ha0, w0.x, b00); b01 = ffma2(ha0, w0.y, b01);
                b10 = ffma2(hb0, w0.x, b10); b11 = ffma2(hb0, w0.y, b11);
                b00 = ffma2(ha1, w1.x, b00); b01 = ffma2(ha1, w1.y, b01);
                b10 = ffma2(hb1, w1.x, b10); b11 = ffma2(hb1, w1.y, b11);
            }
        }

        // epilogue B + publish B
        {
            float ai0, af0, ao0, az0, ai1, af1, ao1, az1;
            upk2(b00, ai0, af0); upk2(b01, ao0, az0);
            upk2(b10, ai1, af1); upk2(b11, ao1, az1);
            float i0 = sigf(ai0), f0 = sigf(af0), o0 = sigf(ao0), z0 = tanhfast(az0);
            cB0 = i0 * z0 + f0 * cB0;
            float h0 = o0 * tanhfast(cB0);
            float i1 = sigf(ai1), f1 = sigf(af1), o1 = sigf(ao1), z1 = tanhfast(az1);
            cB1 = i1 * z1 + f1 * cB1;
            float h1 = o1 * tanhfast(cB1);
            sB0 += h0 * mvB0; mB0 += mvB0;
            sB1 += h1 * mvB1; mB1 += mvB1;
            float2 hv; hv.x = h0; hv.y = h1;
            __stcg((float2*)(g_hbuf + ((size_t)((s + 1) & 1)) * 65536 +
                             (size_t)grpB * 4096 + (size_t)(g * 32 + cq) * 16 + rp * 2),
                   hv);
        }

        __syncthreads();
        if (tid == 0) red_release64(&flagw[myw], myinc);
    }

    int hcol = g * 32 + cq;
    out[(size_t)bA * HH + hcol]       = sA0 * __fdividef(1.0f, mA0);
    out[(size_t)(bA + 1) * HH + hcol] = sA1 * __fdividef(1.0f, mA1);
    out[(size_t)bB * HH + hcol]       = sB0 * __fdividef(1.0f, mB0);
    out[(size_t)(bB + 1) * HH + hcol] = sB1 * __fdividef(1.0f, mB1);
}

// ---------------- launcher ----------------
extern "C" void kernel_launch(void* const* d_in, const int* in_sizes, int n_in,
                              void* d_out, int out_size) {
    const float* x    = (const float*)d_in[0];
    const float* mask = (const float*)d_in[1];
    const float* Wi   = (const float*)d_in[2];
    const float* bi   = (const float*)d_in[3];
    const float* Wf   = (const float*)d_in[4];
    const float* bf   = (const float*)d_in[5];
    const float* Wo   = (const float*)d_in[6];
    const float* bo   = (const float*)d_in[7];
    const float* Wz   = (const float*)d_in[8];
    const float* bz   = (const float*)d_in[9];
    float* out = (float*)d_out;

    cudaFuncSetAttribute(k_rec, cudaFuncAttributeMaxDynamicSharedMemorySize,
                         REC_SMEM_BYTES);

    k_pack<<<(456 * NJ + 255) / 256, 256>>>(Wi, Wf, Wo, Wz, bi, bf, bo, bz);
    k_reset<<<1, 32>>>();
    dim3 g1(NJ / G1_BN, (BB * SS) / G1_BM);
    k_gemm1<<<g1, 256>>>(x);
    k_rec<<<NPAIR * 8, 256, REC_SMEM_BYTES>>>(mask, out);
}

// round 15
// speedup vs baseline: 1.3226x; 1.3226x over previous
#include <cuda_runtime.h>
#include <cstdint>
#include <cstddef>

typedef unsigned long long ull;

// ---------------- constants ----------------
#define BB   256
#define SS   512
#define DD   200
#define HH   256
#define NJ   1024          // 4*H packed gate columns
#define NGRP 16            // batch groups (16 rows each)

// ---------------- device scratch ----------------
__device__ float g_G[134217728];    // [B][S][1024] gate preactivations (x part + bias)
__device__ float g_Wxp[DD * NJ];    // packed x-weights  [200][1024]
__device__ float g_Whp[16 * 16384]; // packed h-weights  [slice16][256 k][64 j]
__device__ float g_biasp[NJ];
__device__ float g_hbuf[2 * 65536]; // [parity][group][col 256][row 16]
__device__ ull   g_flags[64];       // [group][4 words]: 16x16-bit producer counters

// ---------------- helpers ----------------
__device__ __forceinline__ ull pk2(float lo, float hi) {
    ull r; asm("mov.b64 %0,{%1,%2};" : "=l"(r) : "f"(lo), "f"(hi)); return r;
}
__device__ __forceinline__ void upk2(ull v, float& lo, float& hi) {
    asm("mov.b64 {%0,%1},%2;" : "=f"(lo), "=f"(hi) : "l"(v));
}
__device__ __forceinline__ ull ffma2(ull a, ull b, ull c) {
    ull d; asm("fma.rn.f32x2 %0,%1,%2,%3;" : "=l"(d) : "l"(a), "l"(b), "l"(c)); return d;
}
__device__ __forceinline__ float sigf(float x) {
    return __fdividef(1.0f, 1.0f + __expf(-x));
}
__device__ __forceinline__ float tanhfast(float x) {
    return __fdividef(2.0f, 1.0f + __expf(-2.0f * x)) - 1.0f;
}
__device__ __forceinline__ ull ldacq64(const ull* p) {
    ull v;
    asm volatile("ld.global.acquire.gpu.u64 %0,[%1];" : "=l"(v) : "l"(p) : "memory");
    return v;
}
__device__ __forceinline__ void red_release64(ull* p, ull v) {
    asm volatile("red.release.gpu.global.add.u64 [%0], %1;" :: "l"(p), "l"(v) : "memory");
}
__device__ __forceinline__ bool ok16(ull w, unsigned us) {
    return (unsigned)(w & 0xFFFF) >= us && (unsigned)((w >> 16) & 0xFFFF) >= us &&
           (unsigned)((w >> 32) & 0xFFFF) >= us && (unsigned)((w >> 48) & 0xFFFF) >= us;
}
#define HBAR(id) asm volatile("bar.sync %0, 128;" :: "r"(id) : "memory")

// ---------------- kernel 0: pack weights (16-slice layout) ----------------
// j = g2*64 + c*4 + gate  (g2: slice 0..15, c: col-in-slice 0..15, gate: i,f,o,z)
__global__ void k_pack(const float* __restrict__ Wi, const float* __restrict__ Wf,
                       const float* __restrict__ Wo, const float* __restrict__ Wz,
                       const float* __restrict__ bi, const float* __restrict__ bf,
                       const float* __restrict__ bo, const float* __restrict__ bz) {
    int idx = blockIdx.x * blockDim.x + threadIdx.x;
    if (idx < 456 * NJ) {
        int k = idx >> 10;
        int j = idx & (NJ - 1);
        int gate = j & 3;
        int c    = (j >> 2) & 15;
        int g2   = j >> 6;
        int col  = g2 * 16 + c;
        const float* W = (gate == 0) ? Wi : (gate == 1) ? Wf : (gate == 2) ? Wo : Wz;
        float v = W[k * HH + col];
        if (k < DD) g_Wxp[k * NJ + j] = v;
        else        g_Whp[g2 * 16384 + (k - DD) * 64 + (j & 63)] = v;
    }
    if (idx < NJ) {
        int gate = idx & 3;
        int c    = (idx >> 2) & 15;
        int g2   = idx >> 6;
        int col  = g2 * 16 + c;
        const float* bb = (gate == 0) ? bi : (gate == 1) ? bf : (gate == 2) ? bo : bz;
        g_biasp[idx] = bb[col];
    }
}

// ---------------- kernel 1: reset flags ----------------
__global__ void k_reset() {
    int i = threadIdx.x;
    if (i < 64) g_flags[i] = 0ull;
}

// ---------------- kernel 2: G = X @ Wxp + bias (EXACT R4/R10 version) ----------------
#define G1_BM 128
#define G1_BN 64
#define G1_BK 8
__global__ void __launch_bounds__(256) k_gemm1(const float* __restrict__ x) {
    __shared__ __align__(16) float As[2][G1_BK][G1_BM];
    __shared__ __align__(16) float Bs[2][G1_BK][G1_BN];

    int tid = threadIdx.x;
    int m0 = blockIdx.y * G1_BM;
    int n0 = blockIdx.x * G1_BN;

    int arow = tid >> 1;
    int akq  = (tid & 1) * 4;
    const float* aptr = x + (size_t)(m0 + arow) * DD + akq;

    int bkk = tid >> 5;
    int bn  = (tid & 31) * 2;
    const float* bptr = g_Wxp + (size_t)bkk * NJ + n0 + bn;

    int tx = tid & 15;   // 4 n-cols
    int ty = tid >> 4;   // 8 m-rows

    ull acc[4][4];
#pragma unroll
    for (int i = 0; i < 4; ++i)
#pragma unroll
        for (int j = 0; j < 4; ++j) acc[i][j] = 0ull;

    float4 av = *(const float4*)aptr;
    float2 bv = *(const float2*)bptr;
    As[0][akq + 0][arow] = av.x;
    As[0][akq + 1][arow] = av.y;
    As[0][akq + 2][arow] = av.z;
    As[0][akq + 3][arow] = av.w;
    *(float2*)&Bs[0][bkk][bn] = bv;

    for (int kc = 0; kc < 25; ++kc) {
        __syncthreads();
        int cur = kc & 1;
        if (kc < 24) {
            av = *(const float4*)(aptr + (kc + 1) * G1_BK);
            bv = *(const float2*)(bptr + (size_t)(kc + 1) * G1_BK * NJ);
        }
#pragma unroll
        for (int kk = 0; kk < G1_BK; ++kk) {
            const ull* ap2 = (const ull*)&As[cur][kk][ty * 8];
            ull A0 = ap2[0], A1 = ap2[1], A2 = ap2[2], A3 = ap2[3];
            float4 b4 = *(const float4*)&Bs[cur][kk][tx * 4];
            ull B0 = pk2(b4.x, b4.x), B1 = pk2(b4.y, b4.y);
            ull B2 = pk2(b4.z, b4.z), B3 = pk2(b4.w, b4.w);
            acc[0][0] = ffma2(A0, B0, acc[0][0]); acc[0][1] = ffma2(A0, B1, acc[0][1]);
            acc[0][2] = ffma2(A0, B2, acc[0][2]); acc[0][3] = ffma2(A0, B3, acc[0][3]);
            acc[1][0] = ffma2(A1, B0, acc[1][0]); acc[1][1] = ffma2(A1, B1, acc[1][1]);
            acc[1][2] = ffma2(A1, B2, acc[1][2]); acc[1][3] = ffma2(A1, B3, acc[1][3]);
            acc[2][0] = ffma2(A2, B0, acc[2][0]); acc[2][1] = ffma2(A2, B1, acc[2][1]);
            acc[2][2] = ffma2(A2, B2, acc[2][2]); acc[2][3] = ffma2(A2, B3, acc[2][3]);
            acc[3][0] = ffma2(A3, B0, acc[3][0]); acc[3][1] = ffma2(A3, B1, acc[3][1]);
            acc[3][2] = ffma2(A3, B2, acc[3][2]); acc[3][3] = ffma2(A3, B3, acc[3][3]);
        }
        if (kc < 24) {
            int nxt = cur ^ 1;
            As[nxt][akq + 0][arow] = av.x;
            As[nxt][akq + 1][arow] = av.y;
            As[nxt][akq + 2][arow] = av.z;
            As[nxt][akq + 3][arow] = av.w;
            *(float2*)&Bs[nxt][bkk][bn] = bv;
        }
    }

    float4 bias4 = *(const float4*)(g_biasp + n0 + tx * 4);
#pragma unroll
    for (int rp = 0; rp < 4; ++rp) {
        float4 r0, r1;
        upk2(acc[rp][0], r0.x, r1.x);
        upk2(acc[rp][1], r0.y, r1.y);
        upk2(acc[rp][2], r0.z, r1.z);
        upk2(acc[rp][3], r0.w, r1.w);
        r0.x += bias4.x; r0.y += bias4.y; r0.z += bias4.z; r0.w += bias4.w;
        r1.x += bias4.x; r1.y += bias4.y; r1.z += bias4.z; r1.w += bias4.w;
        size_t mrow = (size_t)m0 + ty * 8 + rp * 2;
        __stcs((float4*)(g_G + mrow * NJ + n0 + tx * 4), r0);
        __stcs((float4*)(g_G + (mrow + 1) * NJ + n0 + tx * 4), r1);
    }
}

// ---------------- kernel 3: warp-specialized dual-group recurrence ----------------
// 128 CTAs = 8 pairs x 16 col-slices. Warps 0-3 = group 2p, warps 4-7 = group 2p+1.
// Each half: independent poll / named bars / stage / publish. Ws (64KB) shared.
// Matvec body = proven R10/R11 code (3 LDS.128 per 2k).
// smem: Ws 65536 | stgA 16384 | stgB 16384 = 98304 B
#define REC_SMEM_BYTES (65536 + 16384 + 16384)
__global__ void __launch_bounds__(256, 1) k_rec(const float* __restrict__ mask,
                                                float* __restrict__ out) {
    extern __shared__ __align__(16) float sm[];
    float*  Ws   = sm;                       // [256 k][64 j]
    float4* stg0 = (float4*)(sm + 16384);    // 2 x [128 k2][8 rp]

    int tid  = threadIdx.x;
    int pair = blockIdx.x >> 4;
    int g16  = blockIdx.x & 15;              // column slice (16 hidden cols)
    int half = tid >> 7;                     // 0: group 2p, 1: group 2p+1
    int lt   = tid & 127;
    int grp  = pair * 2 + half;
    int rp   = lt & 7;                       // row pair: rows 2rp, 2rp+1
    int cq   = lt >> 3;                      // hidden col in slice 0..15
    int barid = 1 + half;

    // preload weight slice (once; shared by both halves)
    {
        const float4* wsrc = (const float4*)(g_Whp + (size_t)g16 * 16384);
        float4* wdst = (float4*)Ws;
        for (int i = tid; i < 4096; i += 256) wdst[i] = wsrc[i];
    }
    __syncthreads();

    float4* stg = stg0 + half * 1024;
    int b0 = grp * 16 + rp * 2;
    float c0 = 0.f, c1 = 0.f, sum0 = 0.f, sum1 = 0.f, msum0 = 0.f, msum1 = 0.f;
    const float* gbase = g_G + (size_t)b0 * SS * NJ + g16 * 64 + cq * 4;
    const float* mk0 = mask + (size_t)b0 * SS;
    ull* flagw = &g_flags[grp * 4];
    ull  myinc = 1ull << (16 * (g16 & 3));
    int  myw   = g16 >> 2;
    int  gsw   = lt & 7;                     // gather swizzle (lt owns cols 2lt,2lt+1)

    for (int s = 0; s < SS; ++s) {
        // prefetch this step's x-gate preactivations + mask (independent of h)
        float4 ga = __ldcs((const float4*)(gbase + (size_t)s * NJ));
        float4 gb = __ldcs((const float4*)(gbase + (size_t)SS * NJ + (size_t)s * NJ));
        float mv0 = __ldg(mk0 + s), mv1 = __ldg(mk0 + SS + s);

        ull a00 = pk2(ga.x, ga.y), a01 = pk2(ga.z, ga.w);
        ull a10 = pk2(gb.x, gb.y), a11 = pk2(gb.z, gb.w);

        if (s) {
            // poll all 16 producer fields of THIS group (half-local)
            if (lt == 0) {
                unsigned us = (unsigned)s;
                for (;;) {
                    ull w0 = ldacq64(flagw);
                    ull w1 = ldacq64(flagw + 1);
                    ull w2 = ldacq64(flagw + 2);
                    ull w3 = ldacq64(flagw + 3);
                    if (ok16(w0, us) && ok16(w1, us) && ok16(w2, us) && ok16(w3, us))
                        break;
                }
            }
            HBAR(barid);

            // gather h[s]: thread lt owns cols 2lt,2lt+1 (128B contiguous LDG),
            // repack (hr0[2k],hr1[2k],hr0[2k+1],hr1[2k+1]) per row pair, swizzled.
            {
                const float4* src =
                    (const float4*)(g_hbuf + ((size_t)(s & 1)) * 65536 +
                                    (size_t)grp * 4096) + lt * 8;
                float4 v0 = __ldcg(src + 0);
                float4 v1 = __ldcg(src + 1);
                float4 v2 = __ldcg(src + 2);
                float4 v3 = __ldcg(src + 3);
                float4 u0 = __ldcg(src + 4);
                float4 u1 = __ldcg(src + 5);
                float4 u2 = __ldcg(src + 6);
                float4 u3 = __ldcg(src + 7);
                float4* hd = stg + lt * 8;
                hd[0 ^ gsw] = make_float4(v0.x, v0.y, u0.x, u0.y);
                hd[1 ^ gsw] = make_float4(v0.z, v0.w, u0.z, u0.w);
                hd[2 ^ gsw] = make_float4(v1.x, v1.y, u1.x, u1.y);
                hd[3 ^ gsw] = make_float4(v1.z, v1.w, u1.z, u1.w);
                hd[4 ^ gsw] = make_float4(v2.x, v2.y, u2.x, u2.y);
                hd[5 ^ gsw] = make_float4(v2.z, v2.w, u2.z, u2.w);
                hd[6 ^ gsw] = make_float4(v3.x, v3.y, u3.x, u3.y);
                hd[7 ^ gsw] = make_float4(v3.z, v3.w, u3.z, u3.w);
            }
            HBAR(barid);

            // gates = G + h @ Wh : 2 rows x 4 gate cols (1 hidden col) per thread
            const ulonglong2* wq = (const ulonglong2*)Ws + cq;   // row k at +k*16
#pragma unroll 8
            for (int k2 = 0; k2 < 128; ++k2) {
                ulonglong2 w0 = wq[k2 * 32];        // k=2k2:   (wi,wf),(wo,wz)
                ulonglong2 w1 = wq[k2 * 32 + 16];   // k=2k2+1
                float4 h4 = stg[k2 * 8 + (rp ^ (k2 & 7))];
                ull ha0 = pk2(h4.x, h4.x), hb0 = pk2(h4.y, h4.y);
                ull ha1 = pk2(h4.z, h4.z), hb1 = pk2(h4.w, h4.w);
                a00 = ffma2(ha0, w0.x, a00); a01 = ffma2(ha0, w0.y, a01);
                a10 = ffma2(hb0, w0.x, a10); a11 = ffma2(hb0, w0.y, a11);
                a00 = ffma2(ha1, w1.x, a00); a01 = ffma2(ha1, w1.y, a01);
                a10 = ffma2(hb1, w1.x, a10); a11 = ffma2(hb1, w1.y, a11);
            }
        }

        // nonlinearity + state update (gate order i,f,o,z)
        float ai0, af0, ao0, az0, ai1, af1, ao1, az1;
        upk2(a00, ai0, af0); upk2(a01, ao0, az0);
        upk2(a10, ai1, af1); upk2(a11, ao1, az1);
        float i0 = sigf(ai0), f0 = sigf(af0), o0 = sigf(ao0), z0 = tanhfast(az0);
        c0 = i0 * z0 + f0 * c0;
        float h0 = o0 * tanhfast(c0);
        float i1 = sigf(ai1), f1 = sigf(af1), o1 = sigf(ao1), z1 = tanhfast(az1);
        c1 = i1 * z1 + f1 * c1;
        float h1 = o1 * tanhfast(c1);
        sum0 += h0 * mv0; msum0 += mv0;
        sum1 += h1 * mv1; msum1 += mv1;

        // publish h[s+1]: [col][row] layout, one stcg.64
        float2 hv; hv.x = h0; hv.y = h1;
        __stcg((float2*)(g_hbuf + ((size_t)((s + 1) & 1)) * 65536 + (size_t)grp * 4096 +
                         (size_t)(g16 * 16 + cq) * 16 + rp * 2),
               hv);
        HBAR(barid);
        if (lt == 0) red_release64(&flagw[myw], myinc);
    }

    int hcol = g16 * 16 + cq;
    out[(size_t)b0 * HH + hcol]       = sum0 * __fdividef(1.0f, msum0);
    out[(size_t)(b0 + 1) * HH + hcol] = sum1 * __fdividef(1.0f, msum1);
}

// ---------------- launcher ----------------
extern "C" void kernel_launch(void* const* d_in, const int* in_sizes, int n_in,
                              void* d_out, int out_size) {
    const float* x    = (const float*)d_in[0];
    const float* mask = (const float*)d_in[1];
    const float* Wi   = (const float*)d_in[2];
    const float* bi   = (const float*)d_in[3];
    const float* Wf   = (const float*)d_in[4];
    const float* bf   = (const float*)d_in[5];
    const float* Wo   = (const float*)d_in[6];
    const float* bo   = (const float*)d_in[7];
    const float* Wz   = (const float*)d_in[8];
    const float* bz   = (const float*)d_in[9];
    float* out = (float*)d_out;

    cudaFuncSetAttribute(k_rec, cudaFuncAttributeMaxDynamicSharedMemorySize,
                         REC_SMEM_BYTES);

    k_pack<<<(456 * NJ + 255) / 256, 256>>>(Wi, Wf, Wo, Wz, bi, bf, bo, bz);
    k_reset<<<1, 64>>>();
    dim3 g1(NJ / G1_BN, (BB * SS) / G1_BM);
    k_gemm1<<<g1, 256>>>(x);
    k_rec<<<128, 256, REC_SMEM_BYTES>>>(mask, out);
}

// round 17
// speedup vs baseline: 1.6289x; 1.2315x over previous
#include <cuda_runtime.h>
#include <cuda_bf16.h>
#include <cstdint>
#include <cstddef>

typedef unsigned long long ull;

// ---------------- constants ----------------
#define BB   256
#define SS   512
#define DD   200
#define HH   256
#define NJ   1024          // 4*H packed gate columns
#define NGRP 16            // batch groups (16 rows each)
#define MM   (BB * SS)     // 131072 gemm rows
#define KP   256           // padded K (200 -> 256)

// ---------------- device scratch ----------------
__device__ float          g_G[134217728];    // [m][1024] gate preactivations
__device__ __nv_bfloat16  g_Xhi[33554432];   // [m][256] x hi split
__device__ __nv_bfloat16  g_Xlo[33554432];   // [m][256] x lo split
__device__ __nv_bfloat16  g_Bhi[262144];     // [j 1024][256] W^T hi split (K-major)
__device__ __nv_bfloat16  g_Blo[262144];
__device__ float          g_Whp[8 * 32768];  // packed h-weights [colgrp][256 k][128 j]
__device__ float          g_biasp[NJ];
__device__ float          g_hbuf[2 * 65536]; // [parity][group][col 256][row 16]
__device__ ull            g_flags[32];       // [group][word]: 4x16-bit producer counters

// ---------------- helpers ----------------
__device__ __forceinline__ ull pk2(float lo, float hi) {
    ull r; asm("mov.b64 %0,{%1,%2};" : "=l"(r) : "f"(lo), "f"(hi)); return r;
}
__device__ __forceinline__ void upk2(ull v, float& lo, float& hi) {
    asm("mov.b64 {%0,%1},%2;" : "=f"(lo), "=f"(hi) : "l"(v));
}
__device__ __forceinline__ ull ffma2(ull a, ull b, ull c) {
    ull d; asm("fma.rn.f32x2 %0,%1,%2,%3;" : "=l"(d) : "l"(a), "l"(b), "l"(c)); return d;
}
__device__ __forceinline__ float sigf(float x) {
    return __fdividef(1.0f, 1.0f + __expf(-x));
}
__device__ __forceinline__ float tanhfast(float x) {
    return __fdividef(2.0f, 1.0f + __expf(-2.0f * x)) - 1.0f;
}
__device__ __forceinline__ ull ldacq64(const ull* p) {
    ull v;
    asm volatile("ld.global.acquire.gpu.u64 %0,[%1];" : "=l"(v) : "l"(p) : "memory");
    return v;
}
__device__ __forceinline__ void red_release64(ull* p, ull v) {
    asm volatile("red.release.gpu.global.add.u64 [%0], %1;" :: "l"(p), "l"(v) : "memory");
}
__device__ __forceinline__ bool ok4(ull w, unsigned us) {
    return (unsigned)(w & 0xFFFF) >= us && (unsigned)((w >> 16) & 0xFFFF) >= us &&
           (unsigned)((w >> 32) & 0xFFFF) >= us && (unsigned)((w >> 48) & 0xFFFF) >= us;
}

// bf16 mma: D(f32) += A(bf16) * B(bf16), m16n8k16  (sm_80+ PTX, no arch-specific ops)
#define MMA16816(d, a0, a1, a2, a3, b0, b1) \
    asm volatile("mma.sync.aligned.m16n8k16.row.col.f32.bf16.bf16.f32 " \
                 "{%0,%1,%2,%3}, {%4,%5,%6,%7}, {%8,%9}, {%0,%1,%2,%3};" \
                 : "+f"((d)[0]), "+f"((d)[1]), "+f"((d)[2]), "+f"((d)[3]) \
                 : "r"(a0), "r"(a1), "r"(a2), "r"(a3), "r"(b0), "r"(b1))

// ---------------- kernel 0: pack weights (rec Whp + gemm B splits + bias) ----------------
// j = g*128 + c*4 + gate  (g: col group 0..7, c: col-in-group 0..31, gate: i,f,o,z)
__global__ void k_pack(const float* __restrict__ Wi, const float* __restrict__ Wf,
                       const float* __restrict__ Wo, const float* __restrict__ Wz,
                       const float* __restrict__ bi, const float* __restrict__ bf,
                       const float* __restrict__ bo, const float* __restrict__ bz) {
    int idx = blockIdx.x * blockDim.x + threadIdx.x;
    if (idx < 456 * NJ) {
        int k = idx >> 10;
        int j = idx & (NJ - 1);
        int gate = j & 3;
        int c    = (j >> 2) & 31;
        int g    = j >> 7;
        int col  = g * 32 + c;
        const float* W = (gate == 0) ? Wi : (gate == 1) ? Wf : (gate == 2) ? Wo : Wz;
        float v = W[k * HH + col];
        if (k < DD) {
            __nv_bfloat16 hi = __float2bfloat16_rn(v);
            __nv_bfloat16 lo = __float2bfloat16_rn(v - __bfloat162float(hi));
            g_Bhi[(size_t)j * KP + k] = hi;
            g_Blo[(size_t)j * KP + k] = lo;
        } else {
            g_Whp[g * 32768 + (k - DD) * 128 + (j & 127)] = v;
        }
    }
    if (idx < 57344) {  // zero-pad B rows k=200..255
        int j = idx & 1023;
        int k = DD + (idx >> 10);
        g_Bhi[(size_t)j * KP + k] = __float2bfloat16_rn(0.0f);
        g_Blo[(size_t)j * KP + k] = __float2bfloat16_rn(0.0f);
    }
    if (idx < NJ) {
        int gate = idx & 3;
        int c    = (idx >> 2) & 31;
        int g    = idx >> 7;
        int col  = g * 32 + c;
        const float* bb = (gate == 0) ? bi : (gate == 1) ? bf : (gate == 2) ? bo : bz;
        g_biasp[idx] = bb[col];
    }
}

// ---------------- kernel 1: split x into bf16 hi/lo (zero-padded K) ----------------
__global__ void k_splitx(const float* __restrict__ x) {
    size_t idx = (size_t)blockIdx.x * blockDim.x + threadIdx.x;
    if (idx >= (size_t)MM * KP) return;
    size_t m = idx >> 8;
    int k = (int)(idx & 255);
    float v = (k < DD) ? x[m * DD + k] : 0.0f;
    __nv_bfloat16 hi = __float2bfloat16_rn(v);
    __nv_bfloat16 lo = __float2bfloat16_rn(v - __bfloat162float(hi));
    g_Xhi[idx] = hi;
    g_Xlo[idx] = lo;
}

// ---------------- kernel 2: reset flags ----------------
__global__ void k_reset() {
    int i = threadIdx.x;
    if (i < 32) g_flags[i] = 0ull;
}

// ---------------- kernel 3: tensor-core gemm (mma.sync bf16, 3-term split) ----------------
// CTA tile 128x128, 8 warps (2m x 4n; warp 64x32). K = 16 chunks of 16, double-buffered.
// Staging rows padded to 48B -> conflict-free plain-LDS fragment loads (banks 12r+c).
#define GM_PAD  48
#define GM_REG  6144                 // 128 rows * 48B per region
#define GM_BUF  (4 * GM_REG)         // Ahi | Alo | Bhi | Blo
__global__ void __launch_bounds__(256) k_gemm1m() {
    __shared__ __align__(16) char smc[2 * GM_BUF];   // 49152 B
    int tid  = threadIdx.x;
    int lane = tid & 31;
    int wid  = tid >> 5;
    int wm   = wid & 1;               // m half (64 rows)
    int wn   = wid >> 1;              // n quarter (32 cols)
    int n0 = blockIdx.x * 128;
    int m0 = blockIdx.y * 128;

    float acc[4][4][4];
#pragma unroll
    for (int i = 0; i < 4; ++i)
#pragma unroll
        for (int j = 0; j < 4; ++j)
#pragma unroll
            for (int q = 0; q < 4; ++q) acc[i][j][q] = 0.0f;

    // staging: thread t handles one 16B cell in each region; row = t>>1, khalf = t&1
    int srow = tid >> 1;
    int skq  = tid & 1;
    size_t aoff = ((size_t)(m0 + srow) * KP + skq * 8) * 2;
    size_t boff = ((size_t)(n0 + srow) * KP + skq * 8) * 2;
    const char* pAh = (const char*)g_Xhi + aoff;
    const char* pAl = (const char*)g_Xlo + aoff;
    const char* pBh = (const char*)g_Bhi + boff;
    const char* pBl = (const char*)g_Blo + boff;
    uint32_t sdst = (uint32_t)srow * GM_PAD + skq * 16;

    // prologue: chunk 0
    uint4 vah = *(const uint4*)pAh;
    uint4 val = *(const uint4*)pAl;
    uint4 vbh = *(const uint4*)pBh;
    uint4 vbl = *(const uint4*)pBl;
    *(uint4*)(smc + sdst)              = vah;
    *(uint4*)(smc + GM_REG + sdst)     = val;
    *(uint4*)(smc + 2 * GM_REG + sdst) = vbh;
    *(uint4*)(smc + 3 * GM_REG + sdst) = vbl;

    int gr = lane >> 2;
    int kb = (lane & 3) * 4;

    for (int kc = 0; kc < 16; ++kc) {
        __syncthreads();
        if (kc < 15) {
            size_t ko = (size_t)(kc + 1) * 32;   // 16 bf16 = 32 bytes per chunk
            vah = *(const uint4*)(pAh + ko);
            val = *(const uint4*)(pAl + ko);
            vbh = *(const uint4*)(pBh + ko);
            vbl = *(const uint4*)(pBl + ko);
        }
        const char* buf = smc + (kc & 1) * GM_BUF;

        // B fragments (hi & lo) for 4 n-frags
        uint32_t bh[4][2], bl[4][2];
#pragma unroll
        for (int nf = 0; nf < 4; ++nf) {
            const char* p = buf + 2 * GM_REG + (wn * 32 + nf * 8 + gr) * GM_PAD + kb;
            bh[nf][0] = *(const uint32_t*)p;
            bh[nf][1] = *(const uint32_t*)(p + 16);
            const char* q = p + GM_REG;
            bl[nf][0] = *(const uint32_t*)q;
            bl[nf][1] = *(const uint32_t*)(q + 16);
        }
        // A fragments per m-frag, then 12 MMAs
#pragma unroll
        for (int mf = 0; mf < 4; ++mf) {
            const char* pa = buf + (wm * 64 + mf * 16 + gr) * GM_PAD + kb;
            uint32_t ah0 = *(const uint32_t*)pa;
            uint32_t ah1 = *(const uint32_t*)(pa + 8 * GM_PAD);
            uint32_t ah2 = *(const uint32_t*)(pa + 16);
            uint32_t ah3 = *(const uint32_t*)(pa + 8 * GM_PAD + 16);
            const char* pl = pa + GM_REG;
            uint32_t al0 = *(const uint32_t*)pl;
            uint32_t al1 = *(const uint32_t*)(pl + 8 * GM_PAD);
            uint32_t al2 = *(const uint32_t*)(pl + 16);
            uint32_t al3 = *(const uint32_t*)(pl + 8 * GM_PAD + 16);
#pragma unroll
            for (int nf = 0; nf < 4; ++nf) {
                MMA16816(acc[mf][nf], ah0, ah1, ah2, ah3, bh[nf][0], bh[nf][1]);
                MMA16816(acc[mf][nf], ah0, ah1, ah2, ah3, bl[nf][0], bl[nf][1]);
                MMA16816(acc[mf][nf], al0, al1, al2, al3, bh[nf][0], bh[nf][1]);
            }
        }
        if (kc < 15) {
            char* nb = smc + ((kc + 1) & 1) * GM_BUF;
            *(uint4*)(nb + sdst)              = vah;
            *(uint4*)(nb + GM_REG + sdst)     = val;
            *(uint4*)(nb + 2 * GM_REG + sdst) = vbh;
            *(uint4*)(nb + 3 * GM_REG + sdst) = vbl;
        }
    }

    // epilogue: c0,c1 -> (row, col..col+1); c2,c3 -> row+8
#pragma unroll
    for (int nf = 0; nf < 4; ++nf) {
        int jc = n0 + wn * 32 + nf * 8 + (lane & 3) * 2;
        float2 b2 = *(const float2*)(g_biasp + jc);
#pragma unroll
        for (int mf = 0; mf < 4; ++mf) {
            size_t r0 = (size_t)m0 + wm * 64 + mf * 16 + gr;
            float2 v0, v1;
            v0.x = acc[mf][nf][0] + b2.x; v0.y = acc[mf][nf][1] + b2.y;
            v1.x = acc[mf][nf][2] + b2.x; v1.y = acc[mf][nf][3] + b2.y;
            __stcs((float2*)(g_G + r0 * NJ + jc), v0);
            __stcs((float2*)(g_G + (r0 + 8) * NJ + jc), v1);
        }
    }
}

// ---------------- kernel 4: persistent recurrence (EXACT R11/R12, proven 4148) ----------------
#define REC_SMEM_BYTES (131072 + 16384 + 32768)
__global__ void __launch_bounds__(256, 1) k_rec(const float* __restrict__ mask,
                                                float* __restrict__ out) {
    extern __shared__ __align__(16) float sm[];
    float*  Ws  = sm;                        // [256 k][128 j]
    float4* stg = (float4*)(sm + 32768);     // [2 ph][4 sp][16 k2l][8 rp]
    float*  ms  = sm + 32768 + 4096;         // [512 s][16 r] mask transposed

    int tid = threadIdx.x;
    int grp = blockIdx.x >> 3;
    int g   = blockIdx.x & 7;
    int rp  = tid & 7;
    int cq  = tid >> 3;

    {
        const float4* wsrc = (const float4*)(g_Whp + (size_t)g * 32768);
        float4* wdst = (float4*)Ws;
        for (int i = tid; i < 8192; i += 256) wdst[i] = wsrc[i];
    }
    for (int i = tid; i < 8192; i += 256) {
        int r = i >> 9, s = i & 511;
        ms[s * 16 + r] = mask[(size_t)(grp * 16 + r) * SS + s];
    }
    __syncthreads();

    int b0 = grp * 16 + rp * 2;
    float c0 = 0.f, c1 = 0.f, sum0 = 0.f, sum1 = 0.f, msum0 = 0.f, msum1 = 0.f;
    const float* gbase = g_G + (size_t)b0 * SS * NJ + g * 128 + cq * 4;
    ull* flagw = &g_flags[grp * 2];
    ull  myinc = 1ull << (16 * (g & 3));
    int  myw   = g >> 2;

    int e_sp[2], e_k2l[2], e_rp[2];
#pragma unroll
    for (int q = 0; q < 2; ++q) {
        int e = tid + q * 256;
        e_sp[q]  = e >> 7;
        e_k2l[q] = (e >> 3) & 15;
        e_rp[q]  = e & 7;
    }

    for (int s = 0; s < SS; ++s) {
        float4 ga = __ldcs((const float4*)(gbase + (size_t)s * NJ));
        float4 gb = __ldcs((const float4*)(gbase + (size_t)SS * NJ + (size_t)s * NJ));
        float2 mv = *(const float2*)&ms[s * 16 + rp * 2];

        ull a00 = pk2(ga.x, ga.y), a01 = pk2(ga.z, ga.w);
        ull a10 = pk2(gb.x, gb.y), a11 = pk2(gb.z, gb.w);

        if (s) {
            if (tid == 0) {
                unsigned us = (unsigned)s;
                for (;;) {
                    ull w0 = ldacq64(flagw);
                    ull w1 = ldacq64(flagw + 1);
                    if (ok4(w0, us) && ok4(w1, us)) break;
                }
            }
            __syncthreads();

            const float* hb = g_hbuf + ((size_t)(s & 1)) * 65536 + (size_t)grp * 4096;
            float2 va[4], vb[4];
            int    slot[4];
#pragma unroll
            for (int qq = 0; qq < 4; ++qq) {
                int q  = qq & 1;
                int ph = qq >> 1;
                int jj = (g + ph * 4 + e_sp[q]) & 7;
                const float* src = hb + ((jj * 32 + e_k2l[q] * 2) * 16 + e_rp[q] * 2);
                va[qq] = __ldcg((const float2*)src);
                vb[qq] = __ldcg((const float2*)(src + 16));
                slot[qq] = (ph << 9) + (e_sp[q] * 16 + e_k2l[q]) * 8 +
                           (e_rp[q] ^ (e_k2l[q] & 7));
            }

            stg[slot[0]] = make_float4(va[0].x, va[0].y, vb[0].x, vb[0].y);
            stg[slot[1]] = make_float4(va[1].x, va[1].y, vb[1].x, vb[1].y);
            __syncthreads();

            const ulonglong2* wq = (const ulonglong2*)Ws + cq;
            for (int idx = 0; idx < 4; ++idx) {
                int jj = (g + idx) & 7;
                const ulonglong2* wj = wq + jj * 1024;
                const float4* hq = stg + idx * 128;
#pragma unroll 8
                for (int i = 0; i < 16; ++i) {
                    ulonglong2 w0 = wj[i * 64];
                    ulonglong2 w1 = wj[i * 64 + 32];
                    float4 h4 = hq[i * 8 + (rp ^ (i & 7))];
                    ull ha0 = pk2(h4.x, h4.x), hb0 = pk2(h4.y, h4.y);
                    ull ha1 = pk2(h4.z, h4.z), hb1 = pk2(h4.w, h4.w);
                    a00 = ffma2(ha0, w0.x, a00); a01 = ffma2(ha0, w0.y, a01);
                    a10 = ffma2(hb0, w0.x, a10); a11 = ffma2(hb0, w0.y, a11);
                    a00 = ffma2(ha1, w1.x, a00); a01 = ffma2(ha1, w1.y, a01);
                    a10 = ffma2(hb1, w1.x, a10); a11 = ffma2(hb1, w1.y, a11);
                }
            }

            stg[slot[2]] = make_float4(va[2].x, va[2].y, vb[2].x, vb[2].y);
            stg[slot[3]] = make_float4(va[3].x, va[3].y, vb[3].x, vb[3].y);
            __syncthreads();

            for (int idx = 0; idx < 4; ++idx) {
                int jj = (g + 4 + idx) & 7;
                const ulonglong2* wj = wq + jj * 1024;
                const float4* hq = stg + 512 + idx * 128;
#pragma unroll 8
                for (int i = 0; i < 16; ++i) {
                    ulonglong2 w0 = wj[i * 64];
                    ulonglong2 w1 = wj[i * 64 + 32];
                    float4 h4 = hq[i * 8 + (rp ^ (i & 7))];
                    ull ha0 = pk2(h4.x, h4.x), hb0 = pk2(h4.y, h4.y);
                    ull ha1 = pk2(h4.z, h4.z), hb1 = pk2(h4.w, h4.w);
                    a00 = ffma2(ha0, w0.x, a00); a01 = ffma2(ha0, w0.y, a01);
                    a10 = ffma2(hb0, w0.x, a10); a11 = ffma2(hb0, w0.y, a11);
                    a00 = ffma2(ha1, w1.x, a00); a01 = ffma2(ha1, w1.y, a01);
                    a10 = ffma2(hb1, w1.x, a10); a11 = ffma2(hb1, w1.y, a11);
                }
            }
        }

        float ai0, af0, ao0, az0, ai1, af1, ao1, az1;
        upk2(a00, ai0, af0); upk2(a01, ao0, az0);
        upk2(a10, ai1, af1); upk2(a11, ao1, az1);
        float i0 = sigf(ai0), f0 = sigf(af0), o0 = sigf(ao0), z0 = tanhfast(az0);
        c0 = i0 * z0 + f0 * c0;
        float h0 = o0 * tanhfast(c0);
        float i1 = sigf(ai1), f1 = sigf(af1), o1 = sigf(ao1), z1 = tanhfast(az1);
        c1 = i1 * z1 + f1 * c1;
        float h1 = o1 * tanhfast(c1);
        sum0 += h0 * mv.x; msum0 += mv.x;
        sum1 += h1 * mv.y; msum1 += mv.y;

        float2 hv; hv.x = h0; hv.y = h1;
        __stcg((float2*)(g_hbuf + ((size_t)((s + 1) & 1)) * 65536 + (size_t)grp * 4096 +
                         (size_t)(g * 32 + cq) * 16 + rp * 2),
               hv);
        __syncthreads();
        if (tid == 0) red_release64(&flagw[myw], myinc);
    }

    int hcol = g * 32 + cq;
    out[(size_t)b0 * HH + hcol]       = sum0 * __fdividef(1.0f, msum0);
    out[(size_t)(b0 + 1) * HH + hcol] = sum1 * __fdividef(1.0f, msum1);
}

// ---------------- launcher ----------------
extern "C" void kernel_launch(void* const* d_in, const int* in_sizes, int n_in,
                              void* d_out, int out_size) {
    const float* x    = (const float*)d_in[0];
    const float* mask = (const float*)d_in[1];
    const float* Wi   = (const float*)d_in[2];
    const float* bi   = (const float*)d_in[3];
    const float* Wf   = (const float*)d_in[4];
    const float* bf   = (const float*)d_in[5];
    const float* Wo   = (const float*)d_in[6];
    const float* bo   = (const float*)d_in[7];
    const float* Wz   = (const float*)d_in[8];
    const float* bz   = (const float*)d_in[9];
    float* out = (float*)d_out;

    cudaFuncSetAttribute(k_rec, cudaFuncAttributeMaxDynamicSharedMemorySize,
                         REC_SMEM_BYTES);

    k_pack<<<(456 * NJ + 255) / 256, 256>>>(Wi, Wf, Wo, Wz, bi, bf, bo, bz);
    k_splitx<<<(int)(((size_t)MM * KP + 255) / 256), 256>>>(x);
    k_reset<<<1, 32>>>();
    dim3 gm(NJ / 128, MM / 128);
    k_gemm1m<<<gm, 256>>>();
    k_rec<<<NGRP * 8, 256, REC_SMEM_BYTES>>>(mask, out);
}